// round 1
// baseline (speedup 1.0000x reference)
#include <cuda_runtime.h>
#include <math_constants.h>

// Problem constants (SingleAttention_5179730559541): B=512, T=512, D=128, H=128
#define BB 512
#define TT 512
#define DD 128
#define HH 128

#define NTHREADS 512
#define NWARPS (NTHREADS / 32)

// Block reduce helpers. `sred` must have >= NWARPS floats. Caller must ensure
// no concurrent reuse of sred without a __syncthreads() in between.
__device__ __forceinline__ float blockReduceMax(float v, float* sred) {
    #pragma unroll
    for (int o = 16; o; o >>= 1) v = fmaxf(v, __shfl_xor_sync(0xffffffffu, v, o));
    int warp = threadIdx.x >> 5, lane = threadIdx.x & 31;
    if (lane == 0) sred[warp] = v;
    __syncthreads();
    if (warp == 0) {
        float x = (lane < NWARPS) ? sred[lane] : -CUDART_INF_F;
        #pragma unroll
        for (int o = 8; o; o >>= 1) x = fmaxf(x, __shfl_xor_sync(0xffffffffu, x, o));
        if (lane == 0) sred[0] = x;
    }
    __syncthreads();
    float r = sred[0];
    __syncthreads();
    return r;
}

__device__ __forceinline__ float blockReduceSum(float v, float* sred) {
    #pragma unroll
    for (int o = 16; o; o >>= 1) v += __shfl_xor_sync(0xffffffffu, v, o);
    int warp = threadIdx.x >> 5, lane = threadIdx.x & 31;
    if (lane == 0) sred[warp] = v;
    __syncthreads();
    if (warp == 0) {
        float x = (lane < NWARPS) ? sred[lane] : 0.0f;
        #pragma unroll
        for (int o = 8; o; o >>= 1) x += __shfl_xor_sync(0xffffffffu, x, o);
        if (lane == 0) sred[0] = x;
    }
    __syncthreads();
    float r = sred[0];
    __syncthreads();
    return r;
}

__device__ __forceinline__ int blockReduceSumInt(int v, int* sred) {
    #pragma unroll
    for (int o = 16; o; o >>= 1) v += __shfl_xor_sync(0xffffffffu, v, o);
    int warp = threadIdx.x >> 5, lane = threadIdx.x & 31;
    if (lane == 0) sred[warp] = v;
    __syncthreads();
    if (warp == 0) {
        int x = (lane < NWARPS) ? sred[lane] : 0;
        #pragma unroll
        for (int o = 8; o; o >>= 1) x += __shfl_xor_sync(0xffffffffu, x, o);
        if (lane == 0) sred[0] = x;
    }
    __syncthreads();
    int r = sred[0];
    __syncthreads();
    return r;
}

__global__ __launch_bounds__(NTHREADS, 2)
void single_attention_kernel(const float* __restrict__ input,   // [B,T,D]
                             const int*   __restrict__ mask,    // [B,T]
                             const float* __restrict__ Wt,      // [D,H]
                             const float* __restrict__ Wx,      // [D,H]
                             const float* __restrict__ rate,    // [1]
                             float* __restrict__ out_v,         // [B,D] or null
                             float* __restrict__ out_a)         // [B,T] or null
{
    const int b   = blockIdx.x;
    const int tid = threadIdx.x;
    const int warp = tid >> 5, lane = tid & 31;

    __shared__ float s_q[HH];
    __shared__ float s_lv[DD];
    __shared__ float s_r[DD];
    __shared__ float s_e[TT];
    __shared__ float s_v[4][DD];
    __shared__ float s_redf[NWARPS];
    __shared__ int   s_redi[NWARPS];

    const float* __restrict__ inb = input + (size_t)b * TT * DD;
    const int*   __restrict__ mb  = mask  + (size_t)b * TT;

    // ---- last valid timestep: sum(mask) - 1 ----
    int msum = 0;
    #pragma unroll
    for (int t = tid; t < TT; t += NTHREADS) msum += mb[t];
    msum = blockReduceSumInt(msum, s_redi);
    int last_idx = msum - 1;
    if (last_idx < 0) last_idx = 0;        // clamp (jax gather clamps)

    // ---- last_visit ----
    if (tid < DD) s_lv[tid] = inb[(size_t)last_idx * DD + tid];
    __syncthreads();

    // ---- q[h] = sum_d lv[d] * Wt[d,h]  (threads h: coalesced over Wt rows) ----
    if (tid < HH) {
        float acc = 0.0f;
        #pragma unroll 8
        for (int d = 0; d < DD; d++) acc += s_lv[d] * Wt[d * HH + tid];
        s_q[tid] = acc;
    }
    __syncthreads();

    // ---- r[d] = sum_h Wx[d,h] * q[h] ----
    if (tid < DD) {
        float acc = 0.0f;
        const float4* wrow = reinterpret_cast<const float4*>(Wx + (size_t)tid * HH);
        #pragma unroll 8
        for (int h4 = 0; h4 < HH / 4; h4++) {
            float4 w = wrow[h4];
            acc += w.x * s_q[h4 * 4 + 0] + w.y * s_q[h4 * 4 + 1]
                 + w.z * s_q[h4 * 4 + 2] + w.w * s_q[h4 * 4 + 3];
        }
        s_r[tid] = acc;
    }
    __syncthreads();

    const float srate = 1.0f / (1.0f + expf(-rate[0]));   // sigmoid(rate)

    // ---- phase 1: e[t] = masked score. One warp per t (16 warps round-robin).
    //      dot = input[b,t,:] . r  via float4 + warp reduce.
    {
        const float4 rr = reinterpret_cast<const float4*>(s_r)[lane];
        for (int t = warp; t < TT; t += NWARPS) {
            const float4 x = reinterpret_cast<const float4*>(inb + (size_t)t * DD)[lane];
            float p = x.x * rr.x + x.y * rr.y + x.z * rr.z + x.w * rr.w;
            #pragma unroll
            for (int o = 16; o; o >>= 1) p += __shfl_xor_sync(0xffffffffu, p, o);
            if (lane == 0) {
                float sig   = 1.0f / (1.0f + expf(-p));
                float decay = (float)(TT - t);                    // (T-1-t)+1
                float denom = srate * (logf(2.72f + (1.0f - sig)) * decay);
                float e     = fmaxf(sig / denom, 0.0f);           // relu
                s_e[t] = (mb[t] == 0) ? -1e9f : e;
            }
        }
    }
    __syncthreads();

    // ---- softmax over t ----
    {
        float mx = -CUDART_INF_F;
        for (int t = tid; t < TT; t += NTHREADS) mx = fmaxf(mx, s_e[t]);
        mx = blockReduceMax(mx, s_redf);

        float sum = 0.0f;
        for (int t = tid; t < TT; t += NTHREADS) {
            float ex = expf(s_e[t] - mx);
            s_e[t] = ex;
            sum += ex;
        }
        sum = blockReduceSum(sum, s_redf);
        float inv = 1.0f / sum;
        for (int t = tid; t < TT; t += NTHREADS) {
            float a = s_e[t] * inv;
            s_e[t] = a;
            if (out_a) out_a[(size_t)b * TT + t] = a;
        }
    }
    __syncthreads();

    // ---- phase 2: v[d] = sum_t a[t] * input[b,t,d].
    //      4 t-chunks of 128, 128 d-threads per chunk; coalesced over d.
    {
        const int g = tid >> 7;          // 0..3
        const int d = tid & 127;
        float acc = 0.0f;
        const int t0 = g * (TT / 4), t1 = t0 + (TT / 4);
        #pragma unroll 4
        for (int t = t0; t < t1; t++) {
            acc += s_e[t] * inb[(size_t)t * DD + d];
        }
        s_v[g][d] = acc;
        __syncthreads();
        if (tid < DD && out_v) {
            out_v[(size_t)b * DD + tid] =
                s_v[0][tid] + s_v[1][tid] + s_v[2][tid] + s_v[3][tid];
        }
    }
}

extern "C" void kernel_launch(void* const* d_in, const int* in_sizes, int n_in,
                              void* d_out, int out_size) {
    const float* input = (const float*)d_in[0];
    const int*   mask  = (const int*)  d_in[1];
    const float* Wt    = (const float*)d_in[2];
    const float* Wx    = (const float*)d_in[3];
    const float* rate  = (const float*)d_in[4];

    float* out = (float*)d_out;
    float* out_v = nullptr;
    float* out_a = nullptr;

    if (out_size == BB * DD + BB * TT) {        // (v, a) concatenated
        out_v = out;
        out_a = out + BB * DD;
    } else if (out_size == BB * DD) {           // v only
        out_v = out;
    } else {                                    // a only
        out_a = out;
    }

    single_attention_kernel<<<BB, NTHREADS>>>(input, mask, Wt, Wx, rate, out_v, out_a);
}

// round 2
// speedup vs baseline: 1.6669x; 1.6669x over previous
#include <cuda_runtime.h>
#include <math_constants.h>

// Problem constants: B=512, T=512, D=128, H=128
#define BB 512
#define TT 512
#define DD 128
#define HH 128

#define NTHREADS 512
#define NWARPS 16

#define TS 32                    // timesteps per tile
#define NTILES (TT / TS)         // 16
#define STAGES 3                 // cp.async pipeline depth
#define TILE_FLOATS (TS * DD)    // 4096 floats = 16 KB
#define TILE_F4 (TILE_FLOATS / 4)

// ---------------- cp.async helpers ----------------
__device__ __forceinline__ void cp_async16(void* smem_dst, const void* gmem_src) {
    unsigned s = (unsigned)__cvta_generic_to_shared(smem_dst);
    asm volatile("cp.async.cg.shared.global [%0], [%1], 16;\n" :: "r"(s), "l"(gmem_src));
}
__device__ __forceinline__ void cp_commit() {
    asm volatile("cp.async.commit_group;\n");
}
template <int N>
__device__ __forceinline__ void cp_wait() {
    asm volatile("cp.async.wait_group %0;\n" :: "n"(N));
}

// ---------------- block reduces ----------------
__device__ __forceinline__ float blockReduceSum(float v, float* sred) {
    #pragma unroll
    for (int o = 16; o; o >>= 1) v += __shfl_xor_sync(0xffffffffu, v, o);
    int warp = threadIdx.x >> 5, lane = threadIdx.x & 31;
    if (lane == 0) sred[warp] = v;
    __syncthreads();
    if (warp == 0) {
        float x = (lane < NWARPS) ? sred[lane] : 0.0f;
        #pragma unroll
        for (int o = 8; o; o >>= 1) x += __shfl_xor_sync(0xffffffffu, x, o);
        if (lane == 0) sred[0] = x;
    }
    __syncthreads();
    float r = sred[0];
    __syncthreads();
    return r;
}

__device__ __forceinline__ int blockReduceSumInt(int v, int* sred) {
    #pragma unroll
    for (int o = 16; o; o >>= 1) v += __shfl_xor_sync(0xffffffffu, v, o);
    int warp = threadIdx.x >> 5, lane = threadIdx.x & 31;
    if (lane == 0) sred[warp] = v;
    __syncthreads();
    if (warp == 0) {
        int x = (lane < NWARPS) ? sred[lane] : 0;
        #pragma unroll
        for (int o = 8; o; o >>= 1) x += __shfl_xor_sync(0xffffffffu, x, o);
        if (lane == 0) sred[0] = x;
    }
    __syncthreads();
    int r = sred[0];
    __syncthreads();
    return r;
}

// ---------------- kernel ----------------
__global__ __launch_bounds__(NTHREADS)
void single_attention_kernel(const float* __restrict__ input,   // [B,T,D]
                             const int*   __restrict__ mask,    // [B,T]
                             const float* __restrict__ Wt,      // [D,H]
                             const float* __restrict__ Wx,      // [D,H]
                             const float* __restrict__ rate,    // [1]
                             float* __restrict__ out_v,         // [B,D] or null
                             float* __restrict__ out_a)         // [B,T] or null
{
    extern __shared__ float s_x[];          // STAGES * TILE_FLOATS (tile ring)

    __shared__ float s_w[TT];               // unnormalized softmax weights exp(e)
    __shared__ int   s_m[TT];
    __shared__ float s_q[HH], s_lv[DD], s_r[DD];
    __shared__ float s_qp[4][HH];
    __shared__ float s_rp[4][DD];
    __shared__ float s_redf[NWARPS];
    __shared__ int   s_redi[NWARPS];

    const int b    = blockIdx.x;
    const int tid  = threadIdx.x;
    const int warp = tid >> 5, lane = tid & 31;

    const float* __restrict__ gx = input + (size_t)b * TT * DD;

    // ---- kick off first STAGES-1 tile loads immediately ----
    #pragma unroll
    for (int g = 0; g < STAGES - 1; g++) {
        float4* dst = (float4*)(s_x + (g % STAGES) * TILE_FLOATS);
        const float4* src = (const float4*)(gx + (size_t)g * TILE_FLOATS);
        #pragma unroll
        for (int k = 0; k < TILE_F4 / NTHREADS; k++)
            cp_async16(dst + tid + k * NTHREADS, src + tid + k * NTHREADS);
        cp_commit();
    }

    // ---- prologue (overlapped with the tile loads above) ----
    // mask load + last index
    int mv = mask[(size_t)b * TT + tid];
    s_m[tid] = mv;
    int msum = blockReduceSumInt(mv, s_redi);
    int last = msum - 1; if (last < 0) last = 0;

    if (tid < DD) s_lv[tid] = gx[(size_t)last * DD + tid];
    __syncthreads();

    // q[h] = sum_d lv[d] * Wt[d,h]   (4-way d-chunked partials)
    {
        int c = tid >> 7;            // 0..3
        int h = tid & 127;
        float acc = 0.0f;
        #pragma unroll
        for (int d = c * 32; d < c * 32 + 32; d++)
            acc += s_lv[d] * Wt[d * HH + h];
        s_qp[c][h] = acc;
    }
    __syncthreads();
    if (tid < HH) s_q[tid] = s_qp[0][tid] + s_qp[1][tid] + s_qp[2][tid] + s_qp[3][tid];
    __syncthreads();

    // r[d] = sum_h Wx[d,h] * q[h]   (4-way h-chunked partials, float4)
    {
        int c = tid >> 7;
        int d = tid & 127;
        const float4* wrow = (const float4*)(Wx + (size_t)d * HH) + c * 8;
        const float4* qv   = (const float4*)s_q + c * 8;
        float acc = 0.0f;
        #pragma unroll
        for (int j = 0; j < 8; j++) {
            float4 w = wrow[j], qq = qv[j];
            acc += w.x * qq.x + w.y * qq.y + w.z * qq.z + w.w * qq.w;
        }
        s_rp[c][d] = acc;
    }
    __syncthreads();
    if (tid < DD) s_r[tid] = s_rp[0][tid] + s_rp[1][tid] + s_rp[2][tid] + s_rp[3][tid];
    __syncthreads();

    const float srate = 1.0f / (1.0f + expf(-rate[0]));
    const float4 rr = ((const float4*)s_r)[lane];

    const int g_grp = tid >> 5;      // 0..15 : t-subgroup for accumulation
    const int d4    = tid & 31;      // float4 index over D
    float4 acc = make_float4(0.f, 0.f, 0.f, 0.f);

    // ---- main single pass over input, 3-stage cp.async pipeline ----
    for (int tile = 0; tile < NTILES; ++tile) {
        // issue load for tile+STAGES-1 into its ring slot
        int nt = tile + STAGES - 1;
        if (nt < NTILES) {
            float4* dst = (float4*)(s_x + (nt % STAGES) * TILE_FLOATS);
            const float4* src = (const float4*)(gx + (size_t)nt * TILE_FLOATS);
            #pragma unroll
            for (int k = 0; k < TILE_F4 / NTHREADS; k++)
                cp_async16(dst + tid + k * NTHREADS, src + tid + k * NTHREADS);
        }
        cp_commit();
        cp_wait<STAGES - 1>();
        __syncthreads();                       // tile data visible to all

        const float* sx = s_x + (tile % STAGES) * TILE_FLOATS;
        const int tbase = tile * TS;

        // dots: each warp computes 2 timesteps from SMEM
        {
            int t0 = warp * 2;
            const float4 x0 = ((const float4*)(sx + t0 * DD))[lane];
            const float4 x1 = ((const float4*)(sx + (t0 + 1) * DD))[lane];
            float p0 = x0.x * rr.x + x0.y * rr.y + x0.z * rr.z + x0.w * rr.w;
            float p1 = x1.x * rr.x + x1.y * rr.y + x1.z * rr.z + x1.w * rr.w;
            #pragma unroll
            for (int o = 16; o; o >>= 1) {
                p0 += __shfl_xor_sync(0xffffffffu, p0, o);
                p1 += __shfl_xor_sync(0xffffffffu, p1, o);
            }
            if (lane < 2) {
                float p = (lane == 0) ? p0 : p1;
                int tg = tbase + t0 + lane;
                float w = 0.0f;
                if (s_m[tg] != 0) {
                    float sig   = 1.0f / (1.0f + expf(-p));
                    float decay = (float)(TT - tg);                 // (T-1-t)+1
                    float denom = srate * (logf(2.72f + (1.0f - sig)) * decay);
                    float e     = fmaxf(sig / denom, 0.0f);
                    w = expf(e);                                    // unnormalized weight
                }
                s_w[tg] = w;
            }
        }
        __syncthreads();                       // weights visible

        // weighted accumulate: group g_grp handles 2 timesteps, float4 over D
        {
            int tl = g_grp * 2;
            float w0 = s_w[tbase + tl];
            float w1 = s_w[tbase + tl + 1];
            const float4 xa = ((const float4*)(sx + tl * DD))[d4];
            const float4 xb = ((const float4*)(sx + (tl + 1) * DD))[d4];
            acc.x += w0 * xa.x + w1 * xb.x;
            acc.y += w0 * xa.y + w1 * xb.y;
            acc.z += w0 * xa.z + w1 * xb.z;
            acc.w += w0 * xa.w + w1 * xb.w;
        }
        __syncthreads();                       // done reading sx before overwrite
    }

    // ---- finalize: normalize and write outputs ----
    // park per-group partial v in the (now free) tile ring
    float4* s_red = (float4*)s_x;              // [16 groups][32 float4]
    s_red[g_grp * 32 + d4] = acc;

    float l = blockReduceSum(s_w[tid], s_redf);   // internal barriers publish s_red too
    float inv = 1.0f / l;

    if (out_a) out_a[(size_t)b * TT + tid] = s_w[tid] * inv;

    if (tid < 32 && out_v) {
        float4 v = make_float4(0.f, 0.f, 0.f, 0.f);
        #pragma unroll
        for (int g = 0; g < 16; g++) {
            float4 c = s_red[g * 32 + tid];
            v.x += c.x; v.y += c.y; v.z += c.z; v.w += c.w;
        }
        v.x *= inv; v.y *= inv; v.z *= inv; v.w *= inv;
        ((float4*)(out_v + (size_t)b * DD))[tid] = v;
    }
}

extern "C" void kernel_launch(void* const* d_in, const int* in_sizes, int n_in,
                              void* d_out, int out_size) {
    const float* input = (const float*)d_in[0];
    const int*   mask  = (const int*)  d_in[1];
    const float* Wt    = (const float*)d_in[2];
    const float* Wx    = (const float*)d_in[3];
    const float* rate  = (const float*)d_in[4];

    float* out = (float*)d_out;
    float* out_v = nullptr;
    float* out_a = nullptr;

    if (out_size == BB * DD + BB * TT) {        // (v, a) concatenated
        out_v = out;
        out_a = out + BB * DD;
    } else if (out_size == BB * DD) {           // v only
        out_v = out;
    } else {                                    // a only
        out_a = out;
    }

    static int smem_set = 0;
    const int dyn_smem = STAGES * TILE_FLOATS * sizeof(float);   // 48 KB
    if (!smem_set) {
        cudaFuncSetAttribute(single_attention_kernel,
                             cudaFuncAttributeMaxDynamicSharedMemorySize, dyn_smem);
        smem_set = 1;
    }

    single_attention_kernel<<<BB, NTHREADS, dyn_smem>>>(
        input, mask, Wt, Wx, rate, out_v, out_a);
}

// round 3
// speedup vs baseline: 2.1072x; 1.2642x over previous
#include <cuda_runtime.h>
#include <math_constants.h>

// Problem constants: B=512, T=512, D=128, H=128
#define BB 512
#define TT 512
#define DD 128
#define HH 128

#define NTHREADS 256
#define NWARPS 8
#define ROWS_PER_WARP (TT / NWARPS)     // 64
#define NPAIRS (ROWS_PER_WARP / 2)      // 32

__device__ __forceinline__ float blockReduceSum(float v, float* sred) {
    #pragma unroll
    for (int o = 16; o; o >>= 1) v += __shfl_xor_sync(0xffffffffu, v, o);
    int warp = threadIdx.x >> 5, lane = threadIdx.x & 31;
    if (lane == 0) sred[warp] = v;
    __syncthreads();
    if (warp == 0) {
        float x = (lane < NWARPS) ? sred[lane] : 0.0f;
        #pragma unroll
        for (int o = 4; o; o >>= 1) x += __shfl_xor_sync(0xffffffffu, x, o);
        if (lane == 0) sred[0] = x;
    }
    __syncthreads();
    float r = sred[0];
    __syncthreads();
    return r;
}

__device__ __forceinline__ int blockReduceSumInt(int v, int* sred) {
    #pragma unroll
    for (int o = 16; o; o >>= 1) v += __shfl_xor_sync(0xffffffffu, v, o);
    int warp = threadIdx.x >> 5, lane = threadIdx.x & 31;
    if (lane == 0) sred[warp] = v;
    __syncthreads();
    if (warp == 0) {
        int x = (lane < NWARPS) ? sred[lane] : 0;
        #pragma unroll
        for (int o = 4; o; o >>= 1) x += __shfl_xor_sync(0xffffffffu, x, o);
        if (lane == 0) sred[0] = x;
    }
    __syncthreads();
    int r = sred[0];
    __syncthreads();
    return r;
}

__global__ __launch_bounds__(NTHREADS, 4)
void single_attention_kernel(const float* __restrict__ input,   // [B,T,D]
                             const int*   __restrict__ mask,    // [B,T]
                             const float* __restrict__ Wt,      // [D,H]
                             const float* __restrict__ Wx,      // [D,H]
                             const float* __restrict__ rate,    // [1]
                             float* __restrict__ out_v,         // [B,D] or null
                             float* __restrict__ out_a)         // [B,T] or null
{
    __shared__ float s_w[TT];                // unnormalized weights exp(e)
    __shared__ int   s_m[TT];
    __shared__ float s_q[HH], s_lv[DD], s_r[DD];
    __shared__ float s_qp[2][HH];
    __shared__ float s_rp[2][DD];
    __shared__ float s_vred[NWARPS][DD];     // per-warp partial v
    __shared__ float s_redf[NWARPS];
    __shared__ int   s_redi[NWARPS];

    const int b    = blockIdx.x;
    const int tid  = threadIdx.x;
    const int warp = tid >> 5, lane = tid & 31;

    const float* __restrict__ gx = input + (size_t)b * TT * DD;
    const int*   __restrict__ mb = mask  + (size_t)b * TT;

    // ---------------- prologue: mask, last_visit, q, r ----------------
    int m0 = mb[tid], m1 = mb[tid + 256];
    s_m[tid] = m0; s_m[tid + 256] = m1;
    int msum = blockReduceSumInt(m0 + m1, s_redi);
    int last = msum - 1; if (last < 0) last = 0;

    if (tid < DD) s_lv[tid] = gx[(size_t)last * DD + tid];
    __syncthreads();

    // q[h] = sum_d lv[d] * Wt[d,h]  (2-way d-chunk)
    {
        int c = tid >> 7, h = tid & 127;
        float acc = 0.0f;
        #pragma unroll 8
        for (int d = c * 64; d < c * 64 + 64; d++)
            acc += s_lv[d] * Wt[d * HH + h];
        s_qp[c][h] = acc;
    }
    __syncthreads();
    if (tid < HH) s_q[tid] = s_qp[0][tid] + s_qp[1][tid];
    __syncthreads();

    // r[d] = sum_h Wx[d,h] * q[h]  (2-way h-chunk, float4)
    {
        int c = tid >> 7, d = tid & 127;
        const float4* wrow = (const float4*)(Wx + (size_t)d * HH) + c * 16;
        const float4* qv   = (const float4*)s_q + c * 16;
        float acc = 0.0f;
        #pragma unroll
        for (int j = 0; j < 16; j++) {
            float4 w = wrow[j], qq = qv[j];
            acc += w.x * qq.x + w.y * qq.y + w.z * qq.z + w.w * qq.w;
        }
        s_rp[c][d] = acc;
    }
    __syncthreads();
    if (tid < DD) s_r[tid] = s_rp[0][tid] + s_rp[1][tid];
    __syncthreads();

    const float srate = 1.0f / (1.0f + expf(-rate[0]));
    const float4 rr = ((const float4*)s_r)[lane];
    const int half = lane >> 4;              // 0: row0 of pair, 1: row1
    const int tw0  = warp * ROWS_PER_WARP;   // this warp's first timestep

    // warp's row data as float4: row stride = 32 float4
    const float4* __restrict__ grow = (const float4*)gx + (size_t)tw0 * (DD / 4);

    // ---------------- main loop: warp-autonomous, no barriers ----------------
    float4 xa[2], xb[2];
    xa[0] = grow[0 * 64 + lane];
    xb[0] = grow[0 * 64 + 32 + lane];
    xa[1] = grow[1 * 64 + lane];
    xb[1] = grow[1 * 64 + 32 + lane];

    float4 acc = make_float4(0.f, 0.f, 0.f, 0.f);

    #pragma unroll 4
    for (int i = 0; i < NPAIRS; i++) {
        const int s = i & 1;
        const float4 a  = xa[s];
        const float4 c2 = xb[s];
        if (i + 2 < NPAIRS) {                 // prefetch pair i+2
            xa[s] = grow[(i + 2) * 64 + lane];
            xb[s] = grow[(i + 2) * 64 + 32 + lane];
        }

        // dots of both rows, combined 6-shfl reduce
        float pa = a.x * rr.x + a.y * rr.y + a.z * rr.z + a.w * rr.w;
        float pb = c2.x * rr.x + c2.y * rr.y + c2.z * rr.z + c2.w * rr.w;
        pa += __shfl_xor_sync(0xffffffffu, pa, 16);
        pb += __shfl_xor_sync(0xffffffffu, pb, 16);
        float p = half ? pb : pa;
        p += __shfl_xor_sync(0xffffffffu, p, 8);
        p += __shfl_xor_sync(0xffffffffu, p, 4);
        p += __shfl_xor_sync(0xffffffffu, p, 2);
        p += __shfl_xor_sync(0xffffffffu, p, 1);
        // lanes 0-15 hold dot(t0), lanes 16-31 hold dot(t1)

        const int t = tw0 + 2 * i + half;
        float sig   = 1.0f / (1.0f + expf(-p));
        float denom = srate * (logf(2.72f + (1.0f - sig)) * (float)(TT - t));
        float e     = fmaxf(sig / denom, 0.0f);
        float w     = (s_m[t] != 0) ? expf(e) : 0.0f;

        if ((lane & 15) == 0) s_w[t] = w;
        float w0 = __shfl_sync(0xffffffffu, w, 0);
        float w1 = __shfl_sync(0xffffffffu, w, 16);

        acc.x += w0 * a.x + w1 * c2.x;
        acc.y += w0 * a.y + w1 * c2.y;
        acc.z += w0 * a.z + w1 * c2.z;
        acc.w += w0 * a.w + w1 * c2.w;
    }

    // ---------------- epilogue ----------------
    ((float4*)&s_vred[warp][0])[lane] = acc;
    __syncthreads();                          // publish s_w and s_vred

    float part = s_w[tid] + s_w[tid + 256];
    float l = blockReduceSum(part, s_redf);
    float inv = 1.0f / l;

    if (out_a) {
        out_a[(size_t)b * TT + tid]       = s_w[tid] * inv;
        out_a[(size_t)b * TT + 256 + tid] = s_w[tid + 256] * inv;
    }

    if (out_v && tid < 32) {
        float4 v = make_float4(0.f, 0.f, 0.f, 0.f);
        #pragma unroll
        for (int g = 0; g < NWARPS; g++) {
            float4 c = ((const float4*)&s_vred[g][0])[tid];
            v.x += c.x; v.y += c.y; v.z += c.z; v.w += c.w;
        }
        v.x *= inv; v.y *= inv; v.z *= inv; v.w *= inv;
        ((float4*)(out_v + (size_t)b * DD))[tid] = v;
    }
}

extern "C" void kernel_launch(void* const* d_in, const int* in_sizes, int n_in,
                              void* d_out, int out_size) {
    const float* input = (const float*)d_in[0];
    const int*   mask  = (const int*)  d_in[1];
    const float* Wt    = (const float*)d_in[2];
    const float* Wx    = (const float*)d_in[3];
    const float* rate  = (const float*)d_in[4];

    float* out = (float*)d_out;
    float* out_v = nullptr;
    float* out_a = nullptr;

    if (out_size == BB * DD + BB * TT) {        // (v, a) concatenated
        out_v = out;
        out_a = out + BB * DD;
    } else if (out_size == BB * DD) {           // v only
        out_v = out;
    } else {                                    // a only
        out_a = out;
    }

    single_attention_kernel<<<BB, NTHREADS>>>(input, mask, Wt, Wx, rate, out_v, out_a);
}

// round 4
// speedup vs baseline: 2.3180x; 1.1000x over previous
#include <cuda_runtime.h>
#include <math_constants.h>

// Problem constants: B=512, T=512, D=128, H=128
#define BB 512
#define TT 512
#define DD 128
#define HH 128

#define NTHREADS 256
#define NWARPS 8
#define ROWS_PER_WARP (TT / NWARPS)     // 64
#define NBATCH (ROWS_PER_WARP / 4)      // 16 batches of 4 rows

__device__ __forceinline__ float blockReduceSum(float v, float* sred) {
    #pragma unroll
    for (int o = 16; o; o >>= 1) v += __shfl_xor_sync(0xffffffffu, v, o);
    int warp = threadIdx.x >> 5, lane = threadIdx.x & 31;
    if (lane == 0) sred[warp] = v;
    __syncthreads();
    if (warp == 0) {
        float x = (lane < NWARPS) ? sred[lane] : 0.0f;
        #pragma unroll
        for (int o = 4; o; o >>= 1) x += __shfl_xor_sync(0xffffffffu, x, o);
        if (lane == 0) sred[0] = x;
    }
    __syncthreads();
    float r = sred[0];
    __syncthreads();
    return r;
}

__device__ __forceinline__ int blockReduceSumInt(int v, int* sred) {
    #pragma unroll
    for (int o = 16; o; o >>= 1) v += __shfl_xor_sync(0xffffffffu, v, o);
    int warp = threadIdx.x >> 5, lane = threadIdx.x & 31;
    if (lane == 0) sred[warp] = v;
    __syncthreads();
    if (warp == 0) {
        int x = (lane < NWARPS) ? sred[lane] : 0;
        #pragma unroll
        for (int o = 4; o; o >>= 1) x += __shfl_xor_sync(0xffffffffu, x, o);
        if (lane == 0) sred[0] = x;
    }
    __syncthreads();
    int r = sred[0];
    __syncthreads();
    return r;
}

__global__ __launch_bounds__(NTHREADS, 4)
void single_attention_kernel(const float* __restrict__ input,   // [B,T,D]
                             const int*   __restrict__ mask,    // [B,T]
                             const float* __restrict__ Wt,      // [D,H]
                             const float* __restrict__ Wx,      // [D,H]
                             const float* __restrict__ rate,    // [1]
                             float* __restrict__ out_v,         // [B,D] or null
                             float* __restrict__ out_a)         // [B,T] or null
{
    __shared__ float s_w[TT];                // unnormalized weights exp(e)
    __shared__ int   s_m[TT];
    __shared__ float s_q[HH], s_lv[DD], s_r[DD];
    __shared__ float s_qp[2][HH];
    __shared__ float s_rp[2][DD];
    __shared__ float s_vred[NWARPS][DD];     // per-warp partial v
    __shared__ float s_redf[NWARPS];
    __shared__ int   s_redi[NWARPS];

    const int b    = blockIdx.x;
    const int tid  = threadIdx.x;
    const int warp = tid >> 5, lane = tid & 31;

    const float* __restrict__ gx = input + (size_t)b * TT * DD;
    const int*   __restrict__ mb = mask  + (size_t)b * TT;

    // ---------------- prologue: mask, last_visit, q, r ----------------
    int m0 = mb[tid], m1 = mb[tid + 256];
    s_m[tid] = m0; s_m[tid + 256] = m1;
    int msum = blockReduceSumInt(m0 + m1, s_redi);
    int last = msum - 1; if (last < 0) last = 0;

    if (tid < DD) s_lv[tid] = gx[(size_t)last * DD + tid];
    __syncthreads();

    // q[h] = sum_d lv[d] * Wt[d,h]  (2-way d-chunk)
    {
        int c = tid >> 7, h = tid & 127;
        float acc = 0.0f;
        #pragma unroll 8
        for (int d = c * 64; d < c * 64 + 64; d++)
            acc += s_lv[d] * Wt[d * HH + h];
        s_qp[c][h] = acc;
    }
    __syncthreads();
    if (tid < HH) s_q[tid] = s_qp[0][tid] + s_qp[1][tid];
    __syncthreads();

    // r[d] = sum_h Wx[d,h] * q[h]  (2-way h-chunk, float4)
    {
        int c = tid >> 7, d = tid & 127;
        const float4* wrow = (const float4*)(Wx + (size_t)d * HH) + c * 16;
        const float4* qv   = (const float4*)s_q + c * 16;
        float acc = 0.0f;
        #pragma unroll
        for (int j = 0; j < 16; j++) {
            float4 w = wrow[j], qq = qv[j];
            acc += w.x * qq.x + w.y * qq.y + w.z * qq.z + w.w * qq.w;
        }
        s_rp[c][d] = acc;
    }
    __syncthreads();
    if (tid < DD) s_r[tid] = s_rp[0][tid] + s_rp[1][tid];
    __syncthreads();

    const float srate = __fdividef(1.0f, 1.0f + __expf(-rate[0]));
    const float4 rr = ((const float4*)s_r)[lane];
    const int tw0 = warp * ROWS_PER_WARP;       // this warp's first timestep
    // 8-lane group -> row-in-batch
    const int myrow = ((lane >> 4) & 1) + (((lane >> 3) & 1) << 1);

    const float4* __restrict__ grow = (const float4*)gx + (size_t)tw0 * (DD / 4);

    // ---------------- main loop: warp-autonomous, 4-row batches ----------------
    float4 cur0 = grow[0 * 32 + lane];
    float4 cur1 = grow[1 * 32 + lane];
    float4 cur2 = grow[2 * 32 + lane];
    float4 cur3 = grow[3 * 32 + lane];

    float4 acc0 = make_float4(0.f, 0.f, 0.f, 0.f);
    float4 acc1 = make_float4(0.f, 0.f, 0.f, 0.f);

    #pragma unroll 4
    for (int i = 0; i < NBATCH; i++) {
        // prefetch next batch (clamped reload of last batch on final iter)
        const int ni = (i + 1 < NBATCH) ? i + 1 : NBATCH - 1;
        float4 nxt0 = grow[(ni * 4 + 0) * 32 + lane];
        float4 nxt1 = grow[(ni * 4 + 1) * 32 + lane];
        float4 nxt2 = grow[(ni * 4 + 2) * 32 + lane];
        float4 nxt3 = grow[(ni * 4 + 3) * 32 + lane];

        // 4 dot partials
        float p0 = cur0.x * rr.x + cur0.y * rr.y + cur0.z * rr.z + cur0.w * rr.w;
        float p1 = cur1.x * rr.x + cur1.y * rr.y + cur1.z * rr.z + cur1.w * rr.w;
        float p2 = cur2.x * rr.x + cur2.y * rr.y + cur2.z * rr.z + cur2.w * rr.w;
        float p3 = cur3.x * rr.x + cur3.y * rr.y + cur3.z * rr.z + cur3.w * rr.w;

        // 9-shfl combined reduce: 8-lane group (bits 16,8) owns one row
        p0 += __shfl_xor_sync(0xffffffffu, p0, 16);
        p1 += __shfl_xor_sync(0xffffffffu, p1, 16);
        float v01 = (lane & 16) ? p1 : p0;
        p2 += __shfl_xor_sync(0xffffffffu, p2, 16);
        p3 += __shfl_xor_sync(0xffffffffu, p3, 16);
        float v23 = (lane & 16) ? p3 : p2;
        v01 += __shfl_xor_sync(0xffffffffu, v01, 8);
        v23 += __shfl_xor_sync(0xffffffffu, v23, 8);
        float v = (lane & 8) ? v23 : v01;
        v += __shfl_xor_sync(0xffffffffu, v, 4);
        v += __shfl_xor_sync(0xffffffffu, v, 2);
        v += __shfl_xor_sync(0xffffffffu, v, 1);

        // weight math (fast transcendentals), once per 4 rows
        const int t = tw0 + 4 * i + myrow;
        float sig   = __fdividef(1.0f, 1.0f + __expf(-v));
        float denom = srate * (__logf(2.72f + (1.0f - sig)) * (float)(TT - t));
        float e     = fmaxf(__fdividef(sig, denom), 0.0f);
        float w     = (s_m[t] != 0) ? __expf(e) : 0.0f;

        if ((lane & 7) == 0) s_w[t] = w;     // lanes 0,8,16,24 -> rows 0,2,1,3
        float w0 = __shfl_sync(0xffffffffu, w, 0);
        float w1 = __shfl_sync(0xffffffffu, w, 16);
        float w2 = __shfl_sync(0xffffffffu, w, 8);
        float w3 = __shfl_sync(0xffffffffu, w, 24);

        acc0.x += w0 * cur0.x + w1 * cur1.x;
        acc0.y += w0 * cur0.y + w1 * cur1.y;
        acc0.z += w0 * cur0.z + w1 * cur1.z;
        acc0.w += w0 * cur0.w + w1 * cur1.w;
        acc1.x += w2 * cur2.x + w3 * cur3.x;
        acc1.y += w2 * cur2.y + w3 * cur3.y;
        acc1.z += w2 * cur2.z + w3 * cur3.z;
        acc1.w += w2 * cur2.w + w3 * cur3.w;

        cur0 = nxt0; cur1 = nxt1; cur2 = nxt2; cur3 = nxt3;
    }

    acc0.x += acc1.x; acc0.y += acc1.y; acc0.z += acc1.z; acc0.w += acc1.w;

    // ---------------- epilogue ----------------
    ((float4*)&s_vred[warp][0])[lane] = acc0;
    __syncthreads();                          // publish s_w and s_vred

    float part = s_w[tid] + s_w[tid + 256];
    float l = blockReduceSum(part, s_redf);
    float inv = __fdividef(1.0f, l);

    if (out_a) {
        out_a[(size_t)b * TT + tid]       = s_w[tid] * inv;
        out_a[(size_t)b * TT + 256 + tid] = s_w[tid + 256] * inv;
    }

    if (out_v && tid < 32) {
        float4 v = make_float4(0.f, 0.f, 0.f, 0.f);
        #pragma unroll
        for (int g = 0; g < NWARPS; g++) {
            float4 c = ((const float4*)&s_vred[g][0])[tid];
            v.x += c.x; v.y += c.y; v.z += c.z; v.w += c.w;
        }
        v.x *= inv; v.y *= inv; v.z *= inv; v.w *= inv;
        ((float4*)(out_v + (size_t)b * DD))[tid] = v;
    }
}

extern "C" void kernel_launch(void* const* d_in, const int* in_sizes, int n_in,
                              void* d_out, int out_size) {
    const float* input = (const float*)d_in[0];
    const int*   mask  = (const int*)  d_in[1];
    const float* Wt    = (const float*)d_in[2];
    const float* Wx    = (const float*)d_in[3];
    const float* rate  = (const float*)d_in[4];

    float* out = (float*)d_out;
    float* out_v = nullptr;
    float* out_a = nullptr;

    if (out_size == BB * DD + BB * TT) {        // (v, a) concatenated
        out_v = out;
        out_a = out + BB * DD;
    } else if (out_size == BB * DD) {           // v only
        out_v = out;
    } else {                                    // a only
        out_a = out;
    }

    single_attention_kernel<<<BB, NTHREADS>>>(input, mask, Wt, Wx, rate, out_v, out_a);
}